// round 1
// baseline (speedup 1.0000x reference)
#include <cuda_runtime.h>
#include <math.h>

// Problem constants
#define B_   4096
#define T_   32
#define H_   16
#define HS_  32
#define E_   512
#define M1   (B_ * T_)      // 131072 rows for the big GEMMs
#define K_   512

// Scratch (static __device__ arrays — allocation-free per harness rules)
// g_qkv: [M1][1536]  cols 0..511 = q(h,d), 512..1023 = k, 1024..1535 = v
// g_att: [M1][512]   att2[b*32+d][h*32+t]  (already transposed for final GEMM)
__device__ float g_qkv[(size_t)M1 * 1536];
__device__ float g_att[(size_t)M1 * 512];

// ---------------------------------------------------------------------------
// GEMM: C[m, n] = sum_k A[m,k] * W[n,k]  (+ bias[n])
// A: [M, 512] row-major, W: [N, 512] row-major, C: [M, ldc] (pre-offset base)
// Block tile 128x128x16, 256 threads, 8x8 per-thread micro-tile.
// ---------------------------------------------------------------------------
__global__ void __launch_bounds__(256, 2)
gemm_xwT(const float* __restrict__ A, const float* __restrict__ W,
         float* __restrict__ C, int ldc, const float* __restrict__ bias)
{
    __shared__ float As[16][132];   // [k][m], padded
    __shared__ float Bs[16][132];   // [k][n], padded

    const int m0  = blockIdx.y * 128;
    const int n0  = blockIdx.x * 128;
    const int tid = threadIdx.x;
    const int tx  = tid & 15;    // n micro-tile index
    const int ty  = tid >> 4;    // m micro-tile index

    float acc[8][8];
#pragma unroll
    for (int i = 0; i < 8; i++)
#pragma unroll
        for (int j = 0; j < 8; j++) acc[i][j] = 0.f;

    const int lrow0 = tid >> 2;        // 0..63
    const int lk4   = (tid & 3) << 2;  // 0,4,8,12

    for (int kk = 0; kk < K_; kk += 16) {
#pragma unroll
        for (int i = 0; i < 2; i++) {
            const int row = lrow0 + i * 64;
            float4 av = *(const float4*)(A + (size_t)(m0 + row) * K_ + kk + lk4);
            As[lk4 + 0][row] = av.x; As[lk4 + 1][row] = av.y;
            As[lk4 + 2][row] = av.z; As[lk4 + 3][row] = av.w;
            float4 bv = *(const float4*)(W + (size_t)(n0 + row) * K_ + kk + lk4);
            Bs[lk4 + 0][row] = bv.x; Bs[lk4 + 1][row] = bv.y;
            Bs[lk4 + 2][row] = bv.z; Bs[lk4 + 3][row] = bv.w;
        }
        __syncthreads();
#pragma unroll
        for (int k = 0; k < 16; k++) {
            float a[8], b[8];
            *(float4*)&a[0] = *(const float4*)&As[k][ty * 8 + 0];
            *(float4*)&a[4] = *(const float4*)&As[k][ty * 8 + 4];
            *(float4*)&b[0] = *(const float4*)&Bs[k][tx * 8 + 0];
            *(float4*)&b[4] = *(const float4*)&Bs[k][tx * 8 + 4];
#pragma unroll
            for (int i = 0; i < 8; i++)
#pragma unroll
                for (int j = 0; j < 8; j++)
                    acc[i][j] = fmaf(a[i], b[j], acc[i][j]);
        }
        __syncthreads();
    }

    // Epilogue
    float bv[8];
    if (bias) {
#pragma unroll
        for (int j = 0; j < 8; j++) bv[j] = bias[n0 + tx * 8 + j];
    } else {
#pragma unroll
        for (int j = 0; j < 8; j++) bv[j] = 0.f;
    }
#pragma unroll
    for (int i = 0; i < 8; i++) {
        float4 v0, v1;
        v0.x = acc[i][0] + bv[0]; v0.y = acc[i][1] + bv[1];
        v0.z = acc[i][2] + bv[2]; v0.w = acc[i][3] + bv[3];
        v1.x = acc[i][4] + bv[4]; v1.y = acc[i][5] + bv[5];
        v1.z = acc[i][6] + bv[6]; v1.w = acc[i][7] + bv[7];
        float* crow = C + (size_t)(m0 + ty * 8 + i) * ldc + n0 + tx * 8;
        *(float4*)(crow + 0) = v0;
        *(float4*)(crow + 4) = v1;
    }
}

// ---------------------------------------------------------------------------
// Attention: one CTA (128 threads) per (b,h).
// Reads q,k,v [32,32] tiles from g_qkv, softmax(causal(q k^T / sqrt(32))) v,
// writes the TRANSPOSED head output: att[b*32 + d][h*32 + t] = o[t][d].
// ---------------------------------------------------------------------------
__global__ void __launch_bounds__(128)
attn_kernel(const float* __restrict__ qkv, float* __restrict__ att)
{
    __shared__ float qs[32][33], ks[32][33], vs[32][33], ps[32][33];

    const int bh  = blockIdx.x;
    const int b   = bh >> 4;
    const int h   = bh & 15;
    const int tid = threadIdx.x;

    // Load q,k,v tiles (coalesced 128B rows)
    for (int idx = tid; idx < 1024; idx += 128) {
        const int t = idx >> 5, d = idx & 31;
        const float* row = qkv + (size_t)(b * 32 + t) * 1536 + h * 32 + d;
        qs[t][d] = row[0];
        ks[t][d] = row[512];
        vs[t][d] = row[1024];
    }
    __syncthreads();

    // Each thread: row t = tid/4, 8 score columns s = (tid%4)*8 .. +7
    const int   t     = tid >> 2;
    const int   sg    = tid & 3;
    const float scale = 0.17677669529663687f;  // 32^-0.5
    const float NEG_INF = -__int_as_float(0x7f800000);

    float sv[8];
#pragma unroll
    for (int js = 0; js < 8; js++) {
        const int s = sg * 8 + js;
        float dot = 0.f;
#pragma unroll
        for (int d = 0; d < 32; d++)
            dot = fmaf(qs[t][d], ks[s][d], dot);
        sv[js] = (s <= t) ? dot * scale : NEG_INF;
    }

    // Row softmax: reduce across the 4-thread group (width-4 shuffles)
    float m = sv[0];
#pragma unroll
    for (int js = 1; js < 8; js++) m = fmaxf(m, sv[js]);
    m = fmaxf(m, __shfl_xor_sync(0xffffffffu, m, 1, 4));
    m = fmaxf(m, __shfl_xor_sync(0xffffffffu, m, 2, 4));

    float sum = 0.f;
#pragma unroll
    for (int js = 0; js < 8; js++) { sv[js] = expf(sv[js] - m); sum += sv[js]; }
    sum += __shfl_xor_sync(0xffffffffu, sum, 1, 4);
    sum += __shfl_xor_sync(0xffffffffu, sum, 2, 4);
    const float inv = 1.f / sum;
#pragma unroll
    for (int js = 0; js < 8; js++) ps[t][sg * 8 + js] = sv[js] * inv;
    __syncthreads();

    // O = P * V : thread computes o[t][d] for d = sg*8 .. +7
    float o[8];
#pragma unroll
    for (int j = 0; j < 8; j++) o[j] = 0.f;
#pragma unroll
    for (int s = 0; s < 32; s++) {
        const float p = ps[t][s];
#pragma unroll
        for (int j = 0; j < 8; j++)
            o[j] = fmaf(p, vs[s][sg * 8 + j], o[j]);
    }

    __syncthreads();          // done reading qs — reuse it for the transpose
#pragma unroll
    for (int j = 0; j < 8; j++) qs[sg * 8 + j][t] = o[j];
    __syncthreads();

    // Coalesced transposed store: att[(b*32+d)*512 + h*32 + t]
    for (int idx = tid; idx < 1024; idx += 128) {
        const int d = idx >> 5, tt = idx & 31;
        att[(size_t)(b * 32 + d) * 512 + h * 32 + tt] = qs[d][tt];
    }
}

// ---------------------------------------------------------------------------
// Launch: 3 QKV GEMMs -> attention -> output GEMM (+bias)
// ---------------------------------------------------------------------------
extern "C" void kernel_launch(void* const* d_in, const int* in_sizes, int n_in,
                              void* d_out, int out_size)
{
    const float* x  = (const float*)d_in[0];
    const float* Wq = (const float*)d_in[1];
    const float* Wk = (const float*)d_in[2];
    const float* Wv = (const float*)d_in[3];
    const float* Wp = (const float*)d_in[4];
    const float* bp = (const float*)d_in[5];
    float* out = (float*)d_out;

    float* qkv = nullptr;
    float* att = nullptr;
    cudaGetSymbolAddress((void**)&qkv, g_qkv);
    cudaGetSymbolAddress((void**)&att, g_att);

    const dim3 grid1(4, M1 / 128);   // N=512 tiles x M tiles

    gemm_xwT<<<grid1, 256>>>(x, Wq, qkv + 0,    1536, nullptr);
    gemm_xwT<<<grid1, 256>>>(x, Wk, qkv + 512,  1536, nullptr);
    gemm_xwT<<<grid1, 256>>>(x, Wv, qkv + 1024, 1536, nullptr);

    attn_kernel<<<B_ * H_, 128>>>(qkv, att);

    gemm_xwT<<<grid1, 256>>>(att, Wp, out, 512, bp);
}

// round 3
// speedup vs baseline: 2.3178x; 2.3178x over previous
#include <cuda_runtime.h>
#include <cuda_bf16.h>
#include <stdint.h>
#include <math.h>

// ---------------------------------------------------------------------------
// Problem constants
// ---------------------------------------------------------------------------
#define B_   4096
#define T_   32
#define H_   16
#define E_   512
#define M1   (B_ * T_)      // 131072
#define K_   512

// Packed weight image: [128 n][40 k] bf16 (stride 40 for conflict-free ldmatrix)
#define IMG_ELEMS 5120                     // 128*40
#define IMG_BYTES 10240
#define MATSZ     (4 * 16 * 2 * IMG_ELEMS) // per-matrix: [nt4][kc16][part2] images

// Scratch
__device__ float g_qkv[(size_t)M1 * 1536];
__device__ float g_att[(size_t)M1 * 512];
__device__ __nv_bfloat16 g_wpack[(size_t)4 * MATSZ];

// ---------------------------------------------------------------------------
// Helpers
// ---------------------------------------------------------------------------
__device__ __forceinline__ uint32_t smem_u32(const void* p) {
    uint32_t a;
    asm("{ .reg .u64 t; cvta.to.shared.u64 t, %1; cvt.u32.u64 %0, t; }"
        : "=r"(a) : "l"(p));
    return a;
}

__device__ __forceinline__ void ldsm4(uint32_t addr, uint32_t* r) {
    asm volatile("ldmatrix.sync.aligned.m8n8.x4.shared.b16 {%0,%1,%2,%3}, [%4];"
                 : "=r"(r[0]), "=r"(r[1]), "=r"(r[2]), "=r"(r[3]) : "r"(addr));
}

__device__ __forceinline__ void mma16816(float* d, const uint32_t* a, const uint32_t* b) {
    asm volatile(
        "mma.sync.aligned.m16n8k16.row.col.f32.bf16.bf16.f32 "
        "{%0,%1,%2,%3},{%4,%5,%6,%7},{%8,%9},{%0,%1,%2,%3};"
        : "+f"(d[0]), "+f"(d[1]), "+f"(d[2]), "+f"(d[3])
        : "r"(a[0]), "r"(a[1]), "r"(a[2]), "r"(a[3]), "r"(b[0]), "r"(b[1]));
}

__device__ __forceinline__ void split2(float x, float y, uint32_t& hp, uint32_t& lp) {
    __nv_bfloat16 hx = __float2bfloat16(x);
    __nv_bfloat16 hy = __float2bfloat16(y);
    __nv_bfloat16 lx = __float2bfloat16(x - __bfloat162float(hx));
    __nv_bfloat16 ly = __float2bfloat16(y - __bfloat162float(hy));
    hp = (uint32_t)*(unsigned short*)&hx | ((uint32_t)*(unsigned short*)&hy << 16);
    lp = (uint32_t)*(unsigned short*)&lx | ((uint32_t)*(unsigned short*)&ly << 16);
}

// ---------------------------------------------------------------------------
// Weight pack: W [512n][512k] fp32 -> hi/lo bf16 images [128][40] per
// (nt, kc): dst idx ((nt*16 + kc)*2 + part) * IMG_ELEMS
// grid (16 kc, 4 nt), 128 threads
// ---------------------------------------------------------------------------
__global__ void __launch_bounds__(128)
pack_w(const float* __restrict__ W, __nv_bfloat16* __restrict__ dst)
{
    const int kc = blockIdx.x, nt = blockIdx.y, tid = threadIdx.x;
    char* hi = (char*)(dst + ((size_t)(nt * 16 + kc) * 2 + 0) * IMG_ELEMS);
    char* lo = (char*)(dst + ((size_t)(nt * 16 + kc) * 2 + 1) * IMG_ELEMS);
#pragma unroll
    for (int i = 0; i < 8; i++) {
        const int g = tid + i * 128;
        const int r = g >> 3, c4 = (g & 7) * 4;
        float4 x = *(const float4*)(W + (size_t)(nt * 128 + r) * 512 + kc * 32 + c4);
        uint2 hv, lv;
        split2(x.x, x.y, hv.x, lv.x);
        split2(x.z, x.w, hv.y, lv.y);
        *(uint2*)(hi + r * 80 + c4 * 2) = hv;
        *(uint2*)(lo + r * 80 + c4 * 2) = lv;
    }
}

// ---------------------------------------------------------------------------
// HMMA GEMM: C[m, bx*128 + n] = sum_k A[m,k] * W[n,k]  (bf16 3-split)
// A [M1,512] fp32. wimg = packed images (mat = bx>>2 selects matrix).
// 128 threads, CTA tile 128x128, warp tile 64x64, k-chunk 32, double buffer.
// Smem stage (40960B): Ahi[0] Alo[10240] Bhi[20480] Blo[30720], each [128][40] bf16.
// ---------------------------------------------------------------------------
#define STG_B 40960

__global__ void __launch_bounds__(128)
gemm_hmma(const float* __restrict__ A, const __nv_bfloat16* __restrict__ wimg,
          float* __restrict__ C, int ldc, const float* __restrict__ bias)
{
    extern __shared__ char sm[];
    const uint32_t sb = smem_u32(sm);
    const int tid  = threadIdx.x, lane = tid & 31, wid = tid >> 5;
    const int bx   = blockIdx.x;
    const int m0   = blockIdx.y * 128;
    const int mat  = bx >> 2, nt = bx & 3;
    const int col0 = bx * 128;
    const int wm   = wid & 1, wn = wid >> 1;

    const uint32_t lo_off = (lane & 15) * 80 + (lane >> 4) * 16;

    float acc[4][8][4];
#pragma unroll
    for (int mi = 0; mi < 4; mi++)
#pragma unroll
        for (int ni = 0; ni < 8; ni++)
#pragma unroll
            for (int e = 0; e < 4; e++) acc[mi][ni][e] = 0.f;

    float4 areg[8];

    // ---- helpers as macros over locals ----
#define LOADA(kc_) do {                                                        \
    _Pragma("unroll")                                                          \
    for (int i = 0; i < 8; i++) {                                              \
        const int g = tid + i * 128;                                           \
        const int r = g >> 3, c4 = (g & 7) * 4;                                \
        areg[i] = *(const float4*)(A + (size_t)(m0 + r) * 512 + (kc_) * 32 + c4); \
    } } while (0)

#define CPB(kc_, stg_) do {                                                    \
    const char* _src = (const char*)(wimg +                                    \
        ((size_t)((mat * 4 + nt) * 16 + (kc_)) * 2) * IMG_ELEMS);              \
    const uint32_t _dhi = sb + (stg_) * STG_B + 20480;                         \
    _Pragma("unroll")                                                          \
    for (int i = 0; i < 5; i++) {                                              \
        const int j = (tid + i * 128) * 16;                                    \
        asm volatile("cp.async.cg.shared.global [%0], [%1], 16;"               \
                     :: "r"(_dhi + j), "l"(_src + j));                         \
        asm volatile("cp.async.cg.shared.global [%0], [%1], 16;"               \
                     :: "r"(_dhi + 10240 + j), "l"(_src + IMG_BYTES + j));     \
    }                                                                          \
    asm volatile("cp.async.commit_group;"); } while (0)

#define STOREA(stg_) do {                                                      \
    char* _ab = sm + (stg_) * STG_B;                                           \
    _Pragma("unroll")                                                          \
    for (int i = 0; i < 8; i++) {                                              \
        const int g = tid + i * 128;                                           \
        const int r = g >> 3, c4 = (g & 7) * 4;                                \
        uint2 hv, lv;                                                          \
        split2(areg[i].x, areg[i].y, hv.x, lv.x);                              \
        split2(areg[i].z, areg[i].w, hv.y, lv.y);                              \
        *(uint2*)(_ab + r * 80 + c4 * 2) = hv;                                 \
        *(uint2*)(_ab + 10240 + r * 80 + c4 * 2) = lv;                         \
    } } while (0)

    // ---- prologue: stage 0 ----
    LOADA(0);
    CPB(0, 0);
    STOREA(0);

    for (int kc = 0; kc < 16; kc++) {
        const int cur = kc & 1, nxt = cur ^ 1;
        asm volatile("cp.async.wait_group 0;" ::: "memory");
        __syncthreads();

        if (kc < 15) {
            LOADA(kc + 1);
            CPB(kc + 1, nxt);
        }

        // ---- compute on cur ----
        const uint32_t base = sb + cur * STG_B;
        const uint32_t aAhi = base + (wm * 64) * 80 + lo_off;
        const uint32_t aBhi = base + 20480 + (wn * 64) * 80 + lo_off;
#pragma unroll
        for (int ks2 = 0; ks2 < 2; ks2++) {
            const uint32_t ko = ks2 * 32;   // 16 bf16 = 32 bytes
            uint32_t a[4][4], bh[8][2], bl[8][2];
#pragma unroll
            for (int mi = 0; mi < 4; mi++)
                ldsm4(aAhi + mi * 16 * 80 + ko, a[mi]);
#pragma unroll
            for (int bi = 0; bi < 4; bi++) {
                uint32_t t[4];
                ldsm4(aBhi + bi * 16 * 80 + ko, t);
                bh[2 * bi][0] = t[0]; bh[2 * bi + 1][0] = t[1];
                bh[2 * bi][1] = t[2]; bh[2 * bi + 1][1] = t[3];
            }
#pragma unroll
            for (int mi = 0; mi < 4; mi++)
#pragma unroll
                for (int ni = 0; ni < 8; ni++)
                    mma16816(acc[mi][ni], a[mi], bh[ni]);      // hi*hi
#pragma unroll
            for (int bi = 0; bi < 4; bi++) {
                uint32_t t[4];
                ldsm4(aBhi + 10240 + bi * 16 * 80 + ko, t);    // B lo
                bl[2 * bi][0] = t[0]; bl[2 * bi + 1][0] = t[1];
                bl[2 * bi][1] = t[2]; bl[2 * bi + 1][1] = t[3];
            }
#pragma unroll
            for (int mi = 0; mi < 4; mi++)
#pragma unroll
                for (int ni = 0; ni < 8; ni++)
                    mma16816(acc[mi][ni], a[mi], bl[ni]);      // hi*lo
#pragma unroll
            for (int mi = 0; mi < 4; mi++)
                ldsm4(aAhi + 10240 + mi * 16 * 80 + ko, a[mi]); // A lo
#pragma unroll
            for (int mi = 0; mi < 4; mi++)
#pragma unroll
                for (int ni = 0; ni < 8; ni++)
                    mma16816(acc[mi][ni], a[mi], bh[ni]);      // lo*hi
        }

        if (kc < 15) STOREA(nxt);
    }

    // ---- epilogue: direct fragment stores (float2) ----
    const int rbase = m0 + wm * 64 + (lane >> 2);
    const int cbase = col0 + wn * 64 + (lane & 3) * 2;
#pragma unroll
    for (int ni = 0; ni < 8; ni++) {
        const int col = cbase + ni * 8;
        float b0 = 0.f, b1 = 0.f;
        if (bias) { b0 = bias[col]; b1 = bias[col + 1]; }
#pragma unroll
        for (int mi = 0; mi < 4; mi++) {
            const int row = rbase + mi * 16;
            float2 v0 = make_float2(acc[mi][ni][0] + b0, acc[mi][ni][1] + b1);
            float2 v1 = make_float2(acc[mi][ni][2] + b0, acc[mi][ni][3] + b1);
            *(float2*)(C + (size_t)row * ldc + col)       = v0;
            *(float2*)(C + (size_t)(row + 8) * ldc + col) = v1;
        }
    }
#undef LOADA
#undef CPB
#undef STOREA
}

// ---------------------------------------------------------------------------
// Attention v2: one CTA (128 thr) per (b,h). float4 gmem I/O, q-row in regs,
// ex2.approx with log2e folded into the score scale.
// ---------------------------------------------------------------------------
__global__ void __launch_bounds__(128)
attn_kernel(const float* __restrict__ qkv, float* __restrict__ att)
{
    __shared__ float qs[32][33], ks[32][33], vs[32][33], ps[32][33];

    const int bh  = blockIdx.x;
    const int b   = bh >> 4;
    const int h   = bh & 15;
    const int tid = threadIdx.x;

    // Front-batched float4 loads (6 LDG.128 in flight)
    float4 qv[2], kv[2], vv[2];
#pragma unroll
    for (int i = 0; i < 2; i++) {
        const int g = tid + i * 128;
        const int r = g >> 3, c4 = (g & 7) * 4;
        const float* p = qkv + (size_t)(b * 32 + r) * 1536 + h * 32 + c4;
        qv[i] = *(const float4*)p;
        kv[i] = *(const float4*)(p + 512);
        vv[i] = *(const float4*)(p + 1024);
    }
#pragma unroll
    for (int i = 0; i < 2; i++) {
        const int g = tid + i * 128;
        const int r = g >> 3, c4 = (g & 7) * 4;
        qs[r][c4] = qv[i].x; qs[r][c4+1] = qv[i].y; qs[r][c4+2] = qv[i].z; qs[r][c4+3] = qv[i].w;
        ks[r][c4] = kv[i].x; ks[r][c4+1] = kv[i].y; ks[r][c4+2] = kv[i].z; ks[r][c4+3] = kv[i].w;
        vs[r][c4] = vv[i].x; vs[r][c4+1] = vv[i].y; vs[r][c4+2] = vv[i].z; vs[r][c4+3] = vv[i].w;
    }
    __syncthreads();

    const int t  = tid >> 2;
    const int sg = tid & 3;
    // log2(e) / sqrt(32)
    const float SC = 0.25505654344884233f;
    const float NEG_INF = -__int_as_float(0x7f800000);

    float qr[32];
#pragma unroll
    for (int d = 0; d < 32; d++) qr[d] = qs[t][d];

    float sv[8];
#pragma unroll
    for (int js = 0; js < 8; js++) {
        const int s = sg * 8 + js;
        float dot = 0.f;
#pragma unroll
        for (int d = 0; d < 32; d++)
            dot = fmaf(qr[d], ks[s][d], dot);
        sv[js] = (s <= t) ? dot * SC : NEG_INF;
    }

    float m = sv[0];
#pragma unroll
    for (int js = 1; js < 8; js++) m = fmaxf(m, sv[js]);
    m = fmaxf(m, __shfl_xor_sync(0xffffffffu, m, 1, 4));
    m = fmaxf(m, __shfl_xor_sync(0xffffffffu, m, 2, 4));

    float sum = 0.f;
#pragma unroll
    for (int js = 0; js < 8; js++) {
        float e;
        asm("ex2.approx.ftz.f32 %0, %1;" : "=f"(e) : "f"(sv[js] - m));
        sv[js] = e;
        sum += e;
    }
    sum += __shfl_xor_sync(0xffffffffu, sum, 1, 4);
    sum += __shfl_xor_sync(0xffffffffu, sum, 2, 4);
    const float inv = 1.f / sum;
#pragma unroll
    for (int js = 0; js < 8; js++) ps[t][sg * 8 + js] = sv[js] * inv;
    __syncthreads();

    float o[8];
#pragma unroll
    for (int j = 0; j < 8; j++) o[j] = 0.f;
#pragma unroll
    for (int s = 0; s < 32; s++) {
        const float p = ps[t][s];
#pragma unroll
        for (int j = 0; j < 8; j++)
            o[j] = fmaf(p, vs[s][sg * 8 + j], o[j]);
    }

    __syncthreads();
#pragma unroll
    for (int j = 0; j < 8; j++) qs[sg * 8 + j][t] = o[j];
    __syncthreads();

    // Transposed store, vectorized: att[(b*32+d)*512 + h*32 + tt]
#pragma unroll
    for (int i = 0; i < 2; i++) {
        const int g = tid + i * 128;
        const int d = g >> 3, t4 = (g & 7) * 4;
        float4 w;
        w.x = qs[d][t4]; w.y = qs[d][t4 + 1]; w.z = qs[d][t4 + 2]; w.w = qs[d][t4 + 3];
        *(float4*)(att + (size_t)(b * 32 + d) * 512 + h * 32 + t4) = w;
    }
}

// ---------------------------------------------------------------------------
// Launch
// ---------------------------------------------------------------------------
extern "C" void kernel_launch(void* const* d_in, const int* in_sizes, int n_in,
                              void* d_out, int out_size)
{
    const float* x  = (const float*)d_in[0];
    const float* Wq = (const float*)d_in[1];
    const float* Wk = (const float*)d_in[2];
    const float* Wv = (const float*)d_in[3];
    const float* Wp = (const float*)d_in[4];
    const float* bp = (const float*)d_in[5];
    float* out = (float*)d_out;

    float* qkv = nullptr;
    float* att = nullptr;
    __nv_bfloat16* wpack = nullptr;
    cudaGetSymbolAddress((void**)&qkv, g_qkv);
    cudaGetSymbolAddress((void**)&att, g_att);
    cudaGetSymbolAddress((void**)&wpack, g_wpack);

    cudaFuncSetAttribute(gemm_hmma, cudaFuncAttributeMaxDynamicSharedMemorySize,
                         2 * STG_B);

    pack_w<<<dim3(16, 4), 128>>>(Wq, wpack + 0 * (size_t)MATSZ);
    pack_w<<<dim3(16, 4), 128>>>(Wk, wpack + 1 * (size_t)MATSZ);
    pack_w<<<dim3(16, 4), 128>>>(Wv, wpack + 2 * (size_t)MATSZ);
    pack_w<<<dim3(16, 4), 128>>>(Wp, wpack + 3 * (size_t)MATSZ);

    // QKV fused: bx = mat*4 + ntile, cols bx*128 in qkv (ldc 1536)
    gemm_hmma<<<dim3(12, M1 / 128), 128, 2 * STG_B>>>(x, wpack, qkv, 1536, nullptr);

    attn_kernel<<<B_ * H_, 128>>>(qkv, att);

    // Output projection (+bias)
    gemm_hmma<<<dim3(4, M1 / 128), 128, 2 * STG_B>>>(att, wpack + 3 * (size_t)MATSZ,
                                                     out, 512, bp);
}